// round 1
// baseline (speedup 1.0000x reference)
#include <cuda_runtime.h>

// Problem constants (B=2, T=512, C=256, HID=1024)
constexpr int Mrows = 1024;   // B*T
constexpr int Cdim  = 256;
constexpr int Hdim  = 1024;

// Scratch (static device globals — no allocation allowed)
__device__ float g_h2 [Mrows * Cdim];   // LN output
__device__ float g_hid[Mrows * Hdim];   // relu(h2 @ W1^T + bf1)

// ---------------------------------------------------------------------------
// Kernel 1: xr = x + bp ; h2 = LN(xr)*g2 + b2   (one block per row, 256 thr)
// ---------------------------------------------------------------------------
__global__ void ln_kernel(const float* __restrict__ x,
                          const float* __restrict__ bp,
                          const float* __restrict__ g2,
                          const float* __restrict__ b2)
{
    const int r = blockIdx.x;
    const int c = threadIdx.x;
    float v = x[r * Cdim + c] + bp[c];

    float sum = v, sq = v * v;
    #pragma unroll
    for (int o = 16; o > 0; o >>= 1) {
        sum += __shfl_xor_sync(0xffffffffu, sum, o);
        sq  += __shfl_xor_sync(0xffffffffu, sq,  o);
    }
    __shared__ float s1[8], s2[8];
    const int w = c >> 5;
    if ((c & 31) == 0) { s1[w] = sum; s2[w] = sq; }
    __syncthreads();
    float ts = 0.f, tq = 0.f;
    #pragma unroll
    for (int i = 0; i < 8; i++) { ts += s1[i]; tq += s2[i]; }

    const float mean = ts * (1.0f / Cdim);
    const float var  = tq * (1.0f / Cdim) - mean * mean;
    const float inv  = rsqrtf(var + 1e-5f);
    g_h2[r * Cdim + c] = (v - mean) * inv * g2[c] + b2[c];
}

// ---------------------------------------------------------------------------
// Generic tiled GEMM:  C[m,n] = epilogue( sum_k A[m,k] * B[n,k] )
//   A: [M, Ktot] row-major, B: [Ntot, Ktot] row-major (i.e. computes A @ B^T)
//   MODE 0: relu(acc + bias[n])                      -> Cout
//   MODE 1: acc + resid[m*Ntot+n] + bias[n] + bias2[n] -> Cout
// Smem tiles stored K-outer (As[k][m], Bs[k][n]) for conflict-light reads.
// ---------------------------------------------------------------------------
template <int BM, int BN, int BK, int TM, int TN, int MODE>
__global__ void gemm_kernel(const float* __restrict__ A,
                            const float* __restrict__ B,
                            float* __restrict__ Cout,
                            int Ktot, int Ntot,
                            const float* __restrict__ bias,
                            const float* __restrict__ resid,
                            const float* __restrict__ bias2)
{
    constexpr int NT = (BM / TM) * (BN / TN);   // threads per block (256)
    __shared__ float As[BK][BM];
    __shared__ float Bs[BK][BN];

    const int tid = threadIdx.x;
    const int tx  = tid % (BN / TN);
    const int ty  = tid / (BN / TN);
    const int m0  = blockIdx.y * BM;
    const int n0  = blockIdx.x * BN;

    float acc[TM][TN];
    #pragma unroll
    for (int i = 0; i < TM; i++)
        #pragma unroll
        for (int j = 0; j < TN; j++) acc[i][j] = 0.f;

    for (int k0 = 0; k0 < Ktot; k0 += BK) {
        // Load A tile (float4 along K, transpose into As[k][m])
        #pragma unroll
        for (int idx = tid; idx < BM * BK / 4; idx += NT) {
            const int arow = idx / (BK / 4);
            const int kv   = idx % (BK / 4);
            const float4 v = *reinterpret_cast<const float4*>(
                &A[(size_t)(m0 + arow) * Ktot + k0 + kv * 4]);
            As[kv * 4 + 0][arow] = v.x;
            As[kv * 4 + 1][arow] = v.y;
            As[kv * 4 + 2][arow] = v.z;
            As[kv * 4 + 3][arow] = v.w;
        }
        // Load B tile
        #pragma unroll
        for (int idx = tid; idx < BN * BK / 4; idx += NT) {
            const int brow = idx / (BK / 4);
            const int kv   = idx % (BK / 4);
            const float4 v = *reinterpret_cast<const float4*>(
                &B[(size_t)(n0 + brow) * Ktot + k0 + kv * 4]);
            Bs[kv * 4 + 0][brow] = v.x;
            Bs[kv * 4 + 1][brow] = v.y;
            Bs[kv * 4 + 2][brow] = v.z;
            Bs[kv * 4 + 3][brow] = v.w;
        }
        __syncthreads();

        #pragma unroll
        for (int kk = 0; kk < BK; kk++) {
            float ra[TM], rb[TN];
            #pragma unroll
            for (int i = 0; i < TM; i++) ra[i] = As[kk][ty * TM + i];
            #pragma unroll
            for (int j = 0; j < TN; j++) rb[j] = Bs[kk][tx * TN + j];
            #pragma unroll
            for (int i = 0; i < TM; i++)
                #pragma unroll
                for (int j = 0; j < TN; j++)
                    acc[i][j] += ra[i] * rb[j];
        }
        __syncthreads();
    }

    #pragma unroll
    for (int i = 0; i < TM; i++) {
        const int m = m0 + ty * TM + i;
        #pragma unroll
        for (int j = 0; j < TN; j++) {
            const int n = n0 + tx * TN + j;
            float v = acc[i][j];
            if (MODE == 0) {
                v += bias[n];
                v = v > 0.f ? v : 0.f;
            } else {
                v += resid[(size_t)m * Ntot + n] + bias[n] + bias2[n];
            }
            Cout[(size_t)m * Ntot + n] = v;
        }
    }
}

// ---------------------------------------------------------------------------
// Launch: attention branch is exactly 0 (transform *= 0.0) => sa == bp.
//   y = (x + bp) + relu(LN(x+bp)@W1^T + bf1) @ W2^T + bf2
// Inputs (metadata order):
//   0:x 1:Wt 2:Wp 3:bp 4:g1 5:b1 6:g2 7:b2 8:W1 9:bf1 10:W2 11:bf2
// ---------------------------------------------------------------------------
extern "C" void kernel_launch(void* const* d_in, const int* in_sizes, int n_in,
                              void* d_out, int out_size)
{
    const float* x   = (const float*)d_in[0];
    const float* bp  = (const float*)d_in[3];
    const float* g2  = (const float*)d_in[6];
    const float* b2  = (const float*)d_in[7];
    const float* W1  = (const float*)d_in[8];
    const float* bf1 = (const float*)d_in[9];
    const float* W2  = (const float*)d_in[10];
    const float* bf2 = (const float*)d_in[11];
    float* out = (float*)d_out;

    float *h2p, *hidp;
    cudaGetSymbolAddress((void**)&h2p,  g_h2);
    cudaGetSymbolAddress((void**)&hidp, g_hid);

    // 1) LN over 1024 rows
    ln_kernel<<<Mrows, Cdim>>>(x, bp, g2, b2);

    // 2) hid = relu(h2 @ W1^T + bf1) : M=1024, N=1024, K=256
    gemm_kernel<64, 64, 32, 4, 4, 0><<<dim3(Hdim / 64, Mrows / 64), 256>>>(
        h2p, W1, hidp, Cdim, Hdim, bf1, nullptr, nullptr);

    // 3) out = (x + bp) + hid @ W2^T + bf2 : M=1024, N=256, K=1024
    gemm_kernel<32, 32, 32, 2, 2, 1><<<dim3(Cdim / 32, Mrows / 32), 256>>>(
        hidp, W2, out, Hdim, Cdim, bp, x, bf2);
}

// round 2
// speedup vs baseline: 3.1080x; 3.1080x over previous
#include <cuda_runtime.h>
#include <cuda_bf16.h>
#include <cstdint>

// Problem constants (B=2, T=512, C=256, HID=1024)
constexpr int Mrows = 1024;   // B*T
constexpr int Cdim  = 256;
constexpr int Hdim  = 1024;
constexpr int KSPLIT = 2;     // split-K for GEMM2

// Static device scratch (no allocation allowed)
__device__ __nv_bfloat16 g_h2 [Mrows * Cdim];
__device__ __nv_bfloat16 g_hid[Mrows * Hdim];
__device__ __nv_bfloat16 g_W1 [Hdim * Cdim];
__device__ __nv_bfloat16 g_W2 [Cdim * Hdim];
__device__ float         g_part[KSPLIT * Mrows * Cdim];

// ---------------------------------------------------------------------------
// PTX helpers
// ---------------------------------------------------------------------------
__device__ __forceinline__ uint32_t smem_u32(const void* p) {
    return (uint32_t)__cvta_generic_to_shared(p);
}
__device__ __forceinline__ void ldsm_x4(uint32_t& r0, uint32_t& r1,
                                        uint32_t& r2, uint32_t& r3, uint32_t a) {
    asm volatile("ldmatrix.sync.aligned.m8n8.x4.shared.b16 {%0,%1,%2,%3},[%4];"
                 : "=r"(r0), "=r"(r1), "=r"(r2), "=r"(r3) : "r"(a));
}
__device__ __forceinline__ void ldsm_x2(uint32_t& r0, uint32_t& r1, uint32_t a) {
    asm volatile("ldmatrix.sync.aligned.m8n8.x2.shared.b16 {%0,%1},[%2];"
                 : "=r"(r0), "=r"(r1) : "r"(a));
}
__device__ __forceinline__ void mma_bf16(float* c, const uint32_t* a, const uint32_t* b) {
    asm volatile(
        "mma.sync.aligned.m16n8k16.row.col.f32.bf16.bf16.f32 "
        "{%0,%1,%2,%3},{%4,%5,%6,%7},{%8,%9},{%0,%1,%2,%3};"
        : "+f"(c[0]), "+f"(c[1]), "+f"(c[2]), "+f"(c[3])
        : "r"(a[0]), "r"(a[1]), "r"(a[2]), "r"(a[3]), "r"(b[0]), "r"(b[1]));
}

// ---------------------------------------------------------------------------
// Convert W1 (1024x256) and W2 (256x1024) fp32 -> bf16
// ---------------------------------------------------------------------------
__global__ void convert_kernel(const float* __restrict__ W1,
                               const float* __restrict__ W2)
{
    const int i   = blockIdx.x * blockDim.x + threadIdx.x;   // 131072 threads
    const int idx = i * 4;
    const float* s;
    __nv_bfloat16* d;
    if (idx < Hdim * Cdim) { s = W1 + idx;                 d = g_W1 + idx; }
    else                   { s = W2 + (idx - Hdim * Cdim); d = g_W2 + (idx - Hdim * Cdim); }
    const float4 v = *reinterpret_cast<const float4*>(s);
    __nv_bfloat162 p0, p1;
    p0.x = __float2bfloat16(v.x); p0.y = __float2bfloat16(v.y);
    p1.x = __float2bfloat16(v.z); p1.y = __float2bfloat16(v.w);
    reinterpret_cast<__nv_bfloat162*>(d)[0] = p0;
    reinterpret_cast<__nv_bfloat162*>(d)[1] = p1;
}

// ---------------------------------------------------------------------------
// LN: one warp per row. h2 = LN(x + bp)*g2 + b2  -> bf16
// ---------------------------------------------------------------------------
__global__ void ln_kernel(const float* __restrict__ x,
                          const float* __restrict__ bp,
                          const float* __restrict__ g2,
                          const float* __restrict__ b2)
{
    const int gtid = blockIdx.x * blockDim.x + threadIdx.x;
    const int row  = gtid >> 5;
    const int lane = gtid & 31;
    const int c0   = lane * 8;
    const float* rp = x + (size_t)row * Cdim + c0;

    float v[8];
    {
        const float4 a = *reinterpret_cast<const float4*>(rp);
        const float4 b = *reinterpret_cast<const float4*>(rp + 4);
        const float4 pa = *reinterpret_cast<const float4*>(bp + c0);
        const float4 pb = *reinterpret_cast<const float4*>(bp + c0 + 4);
        v[0] = a.x + pa.x; v[1] = a.y + pa.y; v[2] = a.z + pa.z; v[3] = a.w + pa.w;
        v[4] = b.x + pb.x; v[5] = b.y + pb.y; v[6] = b.z + pb.z; v[7] = b.w + pb.w;
    }
    float s = 0.f, q = 0.f;
    #pragma unroll
    for (int j = 0; j < 8; j++) { s += v[j]; q += v[j] * v[j]; }
    #pragma unroll
    for (int o = 16; o > 0; o >>= 1) {
        s += __shfl_xor_sync(0xffffffffu, s, o);
        q += __shfl_xor_sync(0xffffffffu, q, o);
    }
    const float mean = s * (1.0f / Cdim);
    const float var  = q * (1.0f / Cdim) - mean * mean;
    const float inv  = rsqrtf(var + 1e-5f);

    const float4 ga = *reinterpret_cast<const float4*>(g2 + c0);
    const float4 gb = *reinterpret_cast<const float4*>(g2 + c0 + 4);
    const float4 ba = *reinterpret_cast<const float4*>(b2 + c0);
    const float4 bb = *reinterpret_cast<const float4*>(b2 + c0 + 4);
    const float gg[8] = {ga.x, ga.y, ga.z, ga.w, gb.x, gb.y, gb.z, gb.w};
    const float bbv[8] = {ba.x, ba.y, ba.z, ba.w, bb.x, bb.y, bb.z, bb.w};

    __nv_bfloat162 o[4];
    #pragma unroll
    for (int j = 0; j < 4; j++) {
        o[j].x = __float2bfloat16((v[2*j]   - mean) * inv * gg[2*j]   + bbv[2*j]);
        o[j].y = __float2bfloat16((v[2*j+1] - mean) * inv * gg[2*j+1] + bbv[2*j+1]);
    }
    *reinterpret_cast<uint4*>(&g_h2[(size_t)row * Cdim + c0]) =
        *reinterpret_cast<uint4*>(o);
}

// ---------------------------------------------------------------------------
// bf16 HMMA GEMM:  C[m,n] = sum_k A[m,k]*B[n,k]   (A:[M,K], B:[N,K] row-major)
// MODE 0: relu(acc + bias[n]) -> bf16 Cout
// MODE 1: raw fp32 partial -> Cout + blockIdx.z*Mtot*Ntot  (split-K)
// ---------------------------------------------------------------------------
template <int BM, int BN, int BK, int WM, int WN, int MODE>
__global__ void mma_gemm(const __nv_bfloat16* __restrict__ A,
                         const __nv_bfloat16* __restrict__ B,
                         void* __restrict__ Cout,
                         int Ktot, int Ntot, int Mtot,
                         const float* __restrict__ bias,
                         int ksplit)
{
    constexpr int WARPS_M = BM / WM;
    constexpr int WARPS_N = BN / WN;
    constexpr int NT = WARPS_M * WARPS_N * 32;
    constexpr int LDS = BK + 8;            // bf16 elems per smem row (pad kills conflicts)
    constexpr int MT = WM / 16;
    constexpr int NTt = WN / 8;

    __shared__ __nv_bfloat16 As[BM * LDS];
    __shared__ __nv_bfloat16 Bs[BN * LDS];

    const int tid  = threadIdx.x;
    const int lane = tid & 31;
    const int warp = tid >> 5;
    const int wm   = warp / WARPS_N;
    const int wn   = warp % WARPS_N;
    const int m0   = blockIdx.y * BM;
    const int n0   = blockIdx.x * BN;
    const int kspan = Ktot / ksplit;
    const int kbeg  = blockIdx.z * kspan;

    float acc[MT][NTt][4];
    #pragma unroll
    for (int i = 0; i < MT; i++)
        #pragma unroll
        for (int j = 0; j < NTt; j++)
            #pragma unroll
            for (int r = 0; r < 4; r++) acc[i][j][r] = 0.f;

    for (int k0 = kbeg; k0 < kbeg + kspan; k0 += BK) {
        #pragma unroll
        for (int i = tid; i < BM * BK / 8; i += NT) {
            const int r = i / (BK / 8), cv = i % (BK / 8);
            const uint4 v = *reinterpret_cast<const uint4*>(
                &A[(size_t)(m0 + r) * Ktot + k0 + cv * 8]);
            *reinterpret_cast<uint4*>(&As[r * LDS + cv * 8]) = v;
        }
        #pragma unroll
        for (int i = tid; i < BN * BK / 8; i += NT) {
            const int r = i / (BK / 8), cv = i % (BK / 8);
            const uint4 v = *reinterpret_cast<const uint4*>(
                &B[(size_t)(n0 + r) * Ktot + k0 + cv * 8]);
            *reinterpret_cast<uint4*>(&Bs[r * LDS + cv * 8]) = v;
        }
        __syncthreads();

        #pragma unroll
        for (int ks = 0; ks < BK; ks += 16) {
            uint32_t afrag[MT][4];
            #pragma unroll
            for (int mt = 0; mt < MT; mt++) {
                const int row = wm * WM + mt * 16 + (lane & 15);
                const int col = ks + (lane >> 4) * 8;
                ldsm_x4(afrag[mt][0], afrag[mt][1], afrag[mt][2], afrag[mt][3],
                        smem_u32(&As[row * LDS + col]));
            }
            uint32_t bfrag[NTt][2];
            #pragma unroll
            for (int nt = 0; nt < NTt; nt++) {
                const int row = wn * WN + nt * 8 + (lane & 7);
                const int col = ks + ((lane >> 3) & 1) * 8;
                ldsm_x2(bfrag[nt][0], bfrag[nt][1],
                        smem_u32(&Bs[row * LDS + col]));
            }
            #pragma unroll
            for (int mt = 0; mt < MT; mt++)
                #pragma unroll
                for (int nt = 0; nt < NTt; nt++)
                    mma_bf16(acc[mt][nt], afrag[mt], bfrag[nt]);
        }
        __syncthreads();
    }

    // Epilogue
    #pragma unroll
    for (int mt = 0; mt < MT; mt++) {
        #pragma unroll
        for (int nt = 0; nt < NTt; nt++) {
            const int m = m0 + wm * WM + mt * 16 + (lane >> 2);
            const int n = n0 + wn * WN + nt * 8 + (lane & 3) * 2;
            float c0 = acc[mt][nt][0], c1 = acc[mt][nt][1];
            float c2 = acc[mt][nt][2], c3 = acc[mt][nt][3];
            if (MODE == 0) {
                const float b0 = bias[n], b1 = bias[n + 1];
                c0 = fmaxf(c0 + b0, 0.f); c1 = fmaxf(c1 + b1, 0.f);
                c2 = fmaxf(c2 + b0, 0.f); c3 = fmaxf(c3 + b1, 0.f);
                __nv_bfloat16* O = (__nv_bfloat16*)Cout;
                __nv_bfloat162 p;
                p.x = __float2bfloat16(c0); p.y = __float2bfloat16(c1);
                *reinterpret_cast<__nv_bfloat162*>(&O[(size_t)m * Ntot + n]) = p;
                p.x = __float2bfloat16(c2); p.y = __float2bfloat16(c3);
                *reinterpret_cast<__nv_bfloat162*>(&O[(size_t)(m + 8) * Ntot + n]) = p;
            } else {
                float* O = (float*)Cout + (size_t)blockIdx.z * Mtot * Ntot;
                float2 p;
                p.x = c0; p.y = c1;
                *reinterpret_cast<float2*>(&O[(size_t)m * Ntot + n]) = p;
                p.x = c2; p.y = c3;
                *reinterpret_cast<float2*>(&O[(size_t)(m + 8) * Ntot + n]) = p;
            }
        }
    }
}

// ---------------------------------------------------------------------------
// Final reduce: out = part0 + part1 + x + bp + bf2
// ---------------------------------------------------------------------------
__global__ void reduce_kernel(const float* __restrict__ x,
                              const float* __restrict__ bp,
                              const float* __restrict__ bf2,
                              float* __restrict__ out)
{
    const int i = (blockIdx.x * blockDim.x + threadIdx.x) * 4;
    const int n = i & (Cdim - 1);
    const float4 p0 = *reinterpret_cast<const float4*>(&g_part[i]);
    const float4 p1 = *reinterpret_cast<const float4*>(&g_part[Mrows * Cdim + i]);
    const float4 xv = *reinterpret_cast<const float4*>(&x[i]);
    const float4 bv = *reinterpret_cast<const float4*>(&bp[n]);
    const float4 fv = *reinterpret_cast<const float4*>(&bf2[n]);
    float4 o;
    o.x = p0.x + p1.x + xv.x + bv.x + fv.x;
    o.y = p0.y + p1.y + xv.y + bv.y + fv.y;
    o.z = p0.z + p1.z + xv.z + bv.z + fv.z;
    o.w = p0.w + p1.w + xv.w + bv.w + fv.w;
    *reinterpret_cast<float4*>(&out[i]) = o;
}

// ---------------------------------------------------------------------------
// Attention branch is exactly 0 (transform *= 0.0)  =>  sa == bp.
//   y = (x + bp) + relu(LN(x+bp)@W1^T + bf1) @ W2^T + bf2
// Inputs: 0:x 1:Wt 2:Wp 3:bp 4:g1 5:b1 6:g2 7:b2 8:W1 9:bf1 10:W2 11:bf2
// ---------------------------------------------------------------------------
extern "C" void kernel_launch(void* const* d_in, const int* in_sizes, int n_in,
                              void* d_out, int out_size)
{
    const float* x   = (const float*)d_in[0];
    const float* bp  = (const float*)d_in[3];
    const float* g2  = (const float*)d_in[6];
    const float* b2  = (const float*)d_in[7];
    const float* W1  = (const float*)d_in[8];
    const float* bf1 = (const float*)d_in[9];
    const float* W2  = (const float*)d_in[10];
    const float* bf2 = (const float*)d_in[11];
    float* out = (float*)d_out;

    __nv_bfloat16 *h2p, *hidp, *w1p, *w2p;
    float* partp;
    cudaGetSymbolAddress((void**)&h2p,   g_h2);
    cudaGetSymbolAddress((void**)&hidp,  g_hid);
    cudaGetSymbolAddress((void**)&w1p,   g_W1);
    cudaGetSymbolAddress((void**)&w2p,   g_W2);
    cudaGetSymbolAddress((void**)&partp, g_part);

    // 1) weights fp32 -> bf16   (524288 elems / 4 per thread)
    convert_kernel<<<512, 256>>>(W1, W2);

    // 2) LN (warp per row) -> bf16 h2
    ln_kernel<<<Mrows / 8, 256>>>(x, bp, g2, b2);

    // 3) hid = relu(h2 @ W1^T + bf1) : M=1024, N=1024, K=256 -> bf16
    mma_gemm<64, 128, 32, 32, 32, 0>
        <<<dim3(Hdim / 128, Mrows / 64, 1), 256>>>(
            h2p, w1p, hidp, Cdim, Hdim, Mrows, bf1, 1);

    // 4) partials = hid @ W2^T : M=1024, N=256, K=1024, split-K=2 -> fp32
    mma_gemm<64, 64, 32, 32, 16, 1>
        <<<dim3(Cdim / 64, Mrows / 64, KSPLIT), 256>>>(
            hidp, w2p, partp, Hdim, Cdim, Mrows, nullptr, KSPLIT);

    // 5) out = part0 + part1 + x + bp + bf2
    reduce_kernel<<<Mrows * Cdim / 4 / 256, 256>>>(x, bp, bf2, out);
}

// round 3
// speedup vs baseline: 4.4730x; 1.4392x over previous
#include <cuda_runtime.h>
#include <cuda_bf16.h>
#include <cstdint>

// Problem constants (B=2, T=512, C=256, HID=1024)
constexpr int Mrows = 1024;   // B*T
constexpr int Cdim  = 256;
constexpr int Hdim  = 1024;
constexpr int KSPLIT = 2;     // split-K for GEMM2

// Static device scratch
__device__ __nv_bfloat16 g_h2 [Mrows * Cdim];
__device__ __nv_bfloat16 g_hid[Mrows * Hdim];
__device__ __nv_bfloat16 g_W1 [Hdim * Cdim];
__device__ __nv_bfloat16 g_W2 [Cdim * Hdim];
__device__ float         g_part[KSPLIT * Mrows * Cdim];

// ---------------------------------------------------------------------------
// PTX helpers
// ---------------------------------------------------------------------------
__device__ __forceinline__ uint32_t smem_u32(const void* p) {
    return (uint32_t)__cvta_generic_to_shared(p);
}
__device__ __forceinline__ void ldsm_x4(uint32_t& r0, uint32_t& r1,
                                        uint32_t& r2, uint32_t& r3, uint32_t a) {
    asm volatile("ldmatrix.sync.aligned.m8n8.x4.shared.b16 {%0,%1,%2,%3},[%4];"
                 : "=r"(r0), "=r"(r1), "=r"(r2), "=r"(r3) : "r"(a));
}
__device__ __forceinline__ void ldsm_x2(uint32_t& r0, uint32_t& r1, uint32_t a) {
    asm volatile("ldmatrix.sync.aligned.m8n8.x2.shared.b16 {%0,%1},[%2];"
                 : "=r"(r0), "=r"(r1) : "r"(a));
}
__device__ __forceinline__ void mma_bf16(float* c, const uint32_t* a, const uint32_t* b) {
    asm volatile(
        "mma.sync.aligned.m16n8k16.row.col.f32.bf16.bf16.f32 "
        "{%0,%1,%2,%3},{%4,%5,%6,%7},{%8,%9},{%0,%1,%2,%3};"
        : "+f"(c[0]), "+f"(c[1]), "+f"(c[2]), "+f"(c[3])
        : "r"(a[0]), "r"(a[1]), "r"(a[2]), "r"(a[3]), "r"(b[0]), "r"(b[1]));
}
__device__ __forceinline__ void cp_async16(uint32_t s, const void* g) {
    asm volatile("cp.async.cg.shared.global [%0], [%1], 16;" :: "r"(s), "l"(g));
}
__device__ __forceinline__ void cp_commit() {
    asm volatile("cp.async.commit_group;");
}
template <int N> __device__ __forceinline__ void cp_wait() {
    asm volatile("cp.async.wait_group %0;" :: "n"(N));
}

// ---------------------------------------------------------------------------
// Fused prep kernel:
//   blocks [0, 512)   : convert W1,W2 fp32 -> bf16 (4 floats per thread)
//   blocks [512, 640) : LN, 8 rows per block (one warp per row)
// ---------------------------------------------------------------------------
__global__ void prep_kernel(const float* __restrict__ W1,
                            const float* __restrict__ W2,
                            const float* __restrict__ x,
                            const float* __restrict__ bp,
                            const float* __restrict__ g2,
                            const float* __restrict__ b2)
{
    if (blockIdx.x < 512) {
        const int i   = blockIdx.x * blockDim.x + threadIdx.x;
        const int idx = i * 4;
        const float* s;
        __nv_bfloat16* d;
        if (idx < Hdim * Cdim) { s = W1 + idx;                 d = g_W1 + idx; }
        else                   { s = W2 + (idx - Hdim * Cdim); d = g_W2 + (idx - Hdim * Cdim); }
        const float4 v = *reinterpret_cast<const float4*>(s);
        __nv_bfloat162 p0, p1;
        p0.x = __float2bfloat16(v.x); p0.y = __float2bfloat16(v.y);
        p1.x = __float2bfloat16(v.z); p1.y = __float2bfloat16(v.w);
        reinterpret_cast<__nv_bfloat162*>(d)[0] = p0;
        reinterpret_cast<__nv_bfloat162*>(d)[1] = p1;
        return;
    }
    // LN part
    const int gtid = (blockIdx.x - 512) * blockDim.x + threadIdx.x;
    const int row  = gtid >> 5;
    const int lane = gtid & 31;
    const int c0   = lane * 8;
    const float* rp = x + (size_t)row * Cdim + c0;

    float v[8];
    {
        const float4 a = *reinterpret_cast<const float4*>(rp);
        const float4 b = *reinterpret_cast<const float4*>(rp + 4);
        const float4 pa = *reinterpret_cast<const float4*>(bp + c0);
        const float4 pb = *reinterpret_cast<const float4*>(bp + c0 + 4);
        v[0] = a.x + pa.x; v[1] = a.y + pa.y; v[2] = a.z + pa.z; v[3] = a.w + pa.w;
        v[4] = b.x + pb.x; v[5] = b.y + pb.y; v[6] = b.z + pb.z; v[7] = b.w + pb.w;
    }
    float s = 0.f, q = 0.f;
    #pragma unroll
    for (int j = 0; j < 8; j++) { s += v[j]; q += v[j] * v[j]; }
    #pragma unroll
    for (int o = 16; o > 0; o >>= 1) {
        s += __shfl_xor_sync(0xffffffffu, s, o);
        q += __shfl_xor_sync(0xffffffffu, q, o);
    }
    const float mean = s * (1.0f / Cdim);
    const float var  = q * (1.0f / Cdim) - mean * mean;
    const float inv  = rsqrtf(var + 1e-5f);

    const float4 ga = *reinterpret_cast<const float4*>(g2 + c0);
    const float4 gb = *reinterpret_cast<const float4*>(g2 + c0 + 4);
    const float4 ba = *reinterpret_cast<const float4*>(b2 + c0);
    const float4 bb = *reinterpret_cast<const float4*>(b2 + c0 + 4);
    const float gg[8]  = {ga.x, ga.y, ga.z, ga.w, gb.x, gb.y, gb.z, gb.w};
    const float bbv[8] = {ba.x, ba.y, ba.z, ba.w, bb.x, bb.y, bb.z, bb.w};

    __nv_bfloat162 o[4];
    #pragma unroll
    for (int j = 0; j < 4; j++) {
        o[j].x = __float2bfloat16((v[2*j]   - mean) * inv * gg[2*j]   + bbv[2*j]);
        o[j].y = __float2bfloat16((v[2*j+1] - mean) * inv * gg[2*j+1] + bbv[2*j+1]);
    }
    *reinterpret_cast<uint4*>(&g_h2[(size_t)row * Cdim + c0]) =
        *reinterpret_cast<uint4*>(o);
}

// ---------------------------------------------------------------------------
// Double-buffered cp.async bf16 HMMA GEMM:
//   C[m,n] = sum_k A[m,k]*B[n,k]   (A:[M,K], B:[N,K] row-major)
// MODE 0: relu(acc + bias[n]) -> bf16 Cout
// MODE 1: raw fp32 partial -> Cout + blockIdx.z*Mtot*Ntot  (split-K)
// ---------------------------------------------------------------------------
template <int BM, int BN, int BK, int WM, int WN, int MODE>
__global__ void mma_gemm(const __nv_bfloat16* __restrict__ A,
                         const __nv_bfloat16* __restrict__ B,
                         void* __restrict__ Cout,
                         int Ktot, int Ntot, int Mtot,
                         const float* __restrict__ bias,
                         int ksplit)
{
    constexpr int WARPS_M = BM / WM;
    constexpr int WARPS_N = BN / WN;
    constexpr int NT = WARPS_M * WARPS_N * 32;
    constexpr int LDS = BK + 8;      // bf16 elems per smem row; 144B rows stay 16B-aligned
    constexpr int MT  = WM / 16;
    constexpr int NTt = WN / 8;

    __shared__ __nv_bfloat16 As[2][BM * LDS];
    __shared__ __nv_bfloat16 Bs[2][BN * LDS];

    const int tid  = threadIdx.x;
    const int lane = tid & 31;
    const int warp = tid >> 5;
    const int wm   = warp / WARPS_N;
    const int wn   = warp % WARPS_N;
    const int m0   = blockIdx.y * BM;
    const int n0   = blockIdx.x * BN;
    const int kspan = Ktot / ksplit;
    const int kbeg  = blockIdx.z * kspan;
    const int kIters = kspan / BK;

    auto load_stage = [&](int buf, int k0) {
        #pragma unroll
        for (int i = tid; i < BM * BK / 8; i += NT) {
            const int r = i / (BK / 8), cv = i % (BK / 8);
            cp_async16(smem_u32(&As[buf][r * LDS + cv * 8]),
                       &A[(size_t)(m0 + r) * Ktot + k0 + cv * 8]);
        }
        #pragma unroll
        for (int i = tid; i < BN * BK / 8; i += NT) {
            const int r = i / (BK / 8), cv = i % (BK / 8);
            cp_async16(smem_u32(&Bs[buf][r * LDS + cv * 8]),
                       &B[(size_t)(n0 + r) * Ktot + k0 + cv * 8]);
        }
        cp_commit();
    };

    float acc[MT][NTt][4];
    #pragma unroll
    for (int i = 0; i < MT; i++)
        #pragma unroll
        for (int j = 0; j < NTt; j++)
            #pragma unroll
            for (int r = 0; r < 4; r++) acc[i][j][r] = 0.f;

    load_stage(0, kbeg);

    for (int it = 0; it < kIters; it++) {
        const int buf = it & 1;
        if (it + 1 < kIters) {
            load_stage((it + 1) & 1, kbeg + (it + 1) * BK);
            cp_wait<1>();
        } else {
            cp_wait<0>();
        }
        __syncthreads();

        #pragma unroll
        for (int ks = 0; ks < BK; ks += 16) {
            uint32_t afrag[MT][4];
            #pragma unroll
            for (int mt = 0; mt < MT; mt++) {
                const int row = wm * WM + mt * 16 + (lane & 15);
                const int col = ks + (lane >> 4) * 8;
                ldsm_x4(afrag[mt][0], afrag[mt][1], afrag[mt][2], afrag[mt][3],
                        smem_u32(&As[buf][row * LDS + col]));
            }
            uint32_t bfrag[NTt][2];
            #pragma unroll
            for (int nt = 0; nt < NTt; nt++) {
                const int row = wn * WN + nt * 8 + (lane & 7);
                const int col = ks + ((lane >> 3) & 1) * 8;
                ldsm_x2(bfrag[nt][0], bfrag[nt][1],
                        smem_u32(&Bs[buf][row * LDS + col]));
            }
            #pragma unroll
            for (int mt = 0; mt < MT; mt++)
                #pragma unroll
                for (int nt = 0; nt < NTt; nt++)
                    mma_bf16(acc[mt][nt], afrag[mt], bfrag[nt]);
        }
        __syncthreads();
    }

    // Epilogue
    #pragma unroll
    for (int mt = 0; mt < MT; mt++) {
        #pragma unroll
        for (int nt = 0; nt < NTt; nt++) {
            const int m = m0 + wm * WM + mt * 16 + (lane >> 2);
            const int n = n0 + wn * WN + nt * 8 + (lane & 3) * 2;
            float c0 = acc[mt][nt][0], c1 = acc[mt][nt][1];
            float c2 = acc[mt][nt][2], c3 = acc[mt][nt][3];
            if (MODE == 0) {
                const float b0 = bias[n], b1 = bias[n + 1];
                c0 = fmaxf(c0 + b0, 0.f); c1 = fmaxf(c1 + b1, 0.f);
                c2 = fmaxf(c2 + b0, 0.f); c3 = fmaxf(c3 + b1, 0.f);
                __nv_bfloat16* O = (__nv_bfloat16*)Cout;
                __nv_bfloat162 p;
                p.x = __float2bfloat16(c0); p.y = __float2bfloat16(c1);
                *reinterpret_cast<__nv_bfloat162*>(&O[(size_t)m * Ntot + n]) = p;
                p.x = __float2bfloat16(c2); p.y = __float2bfloat16(c3);
                *reinterpret_cast<__nv_bfloat162*>(&O[(size_t)(m + 8) * Ntot + n]) = p;
            } else {
                float* O = (float*)Cout + (size_t)blockIdx.z * Mtot * Ntot;
                float2 p;
                p.x = c0; p.y = c1;
                *reinterpret_cast<float2*>(&O[(size_t)m * Ntot + n]) = p;
                p.x = c2; p.y = c3;
                *reinterpret_cast<float2*>(&O[(size_t)(m + 8) * Ntot + n]) = p;
            }
        }
    }
}

// ---------------------------------------------------------------------------
// Final reduce: out = part0 + part1 + x + bp + bf2
// ---------------------------------------------------------------------------
__global__ void reduce_kernel(const float* __restrict__ x,
                              const float* __restrict__ bp,
                              const float* __restrict__ bf2,
                              float* __restrict__ out)
{
    const int i = (blockIdx.x * blockDim.x + threadIdx.x) * 4;
    const int n = i & (Cdim - 1);
    const float4 p0 = *reinterpret_cast<const float4*>(&g_part[i]);
    const float4 p1 = *reinterpret_cast<const float4*>(&g_part[Mrows * Cdim + i]);
    const float4 xv = *reinterpret_cast<const float4*>(&x[i]);
    const float4 bv = *reinterpret_cast<const float4*>(&bp[n]);
    const float4 fv = *reinterpret_cast<const float4*>(&bf2[n]);
    float4 o;
    o.x = p0.x + p1.x + xv.x + bv.x + fv.x;
    o.y = p0.y + p1.y + xv.y + bv.y + fv.y;
    o.z = p0.z + p1.z + xv.z + bv.z + fv.z;
    o.w = p0.w + p1.w + xv.w + bv.w + fv.w;
    *reinterpret_cast<float4*>(&out[i]) = o;
}

// ---------------------------------------------------------------------------
// Attention branch is exactly 0 (transform *= 0.0)  =>  sa == bp.
//   y = (x + bp) + relu(LN(x+bp)@W1^T + bf1) @ W2^T + bf2
// Inputs: 0:x 1:Wt 2:Wp 3:bp 4:g1 5:b1 6:g2 7:b2 8:W1 9:bf1 10:W2 11:bf2
// ---------------------------------------------------------------------------
extern "C" void kernel_launch(void* const* d_in, const int* in_sizes, int n_in,
                              void* d_out, int out_size)
{
    const float* x   = (const float*)d_in[0];
    const float* bp  = (const float*)d_in[3];
    const float* g2  = (const float*)d_in[6];
    const float* b2  = (const float*)d_in[7];
    const float* W1  = (const float*)d_in[8];
    const float* bf1 = (const float*)d_in[9];
    const float* W2  = (const float*)d_in[10];
    const float* bf2 = (const float*)d_in[11];
    float* out = (float*)d_out;

    __nv_bfloat16 *h2p, *hidp, *w1p, *w2p;
    float* partp;
    cudaGetSymbolAddress((void**)&h2p,   g_h2);
    cudaGetSymbolAddress((void**)&hidp,  g_hid);
    cudaGetSymbolAddress((void**)&w1p,   g_W1);
    cudaGetSymbolAddress((void**)&w2p,   g_W2);
    cudaGetSymbolAddress((void**)&partp, g_part);

    // 1) fused: convert W1,W2 -> bf16  +  LN -> bf16 h2
    prep_kernel<<<512 + 128, 256>>>(W1, W2, x, bp, g2, b2);

    // 2) hid = relu(h2 @ W1^T + bf1) : M=1024, N=1024, K=256 -> bf16
    mma_gemm<64, 128, 64, 32, 32, 0>
        <<<dim3(Hdim / 128, Mrows / 64, 1), 256>>>(
            h2p, w1p, hidp, Cdim, Hdim, Mrows, bf1, 1);

    // 3) partials = hid @ W2^T : M=1024, N=256, K=1024, split-K=2 -> fp32
    mma_gemm<64, 64, 64, 32, 16, 1>
        <<<dim3(Cdim / 64, Mrows / 64, KSPLIT), 256>>>(
            hidp, w2p, partp, Hdim, Cdim, Mrows, nullptr, KSPLIT);

    // 4) out = part0 + part1 + x + bp + bf2
    reduce_kernel<<<Mrows * Cdim / 4 / 256, 256>>>(x, bp, bf2, out);
}